// round 10
// baseline (speedup 1.0000x reference)
#include <cuda_runtime.h>
#include <cuda_bf16.h>
#include <cstdint>
#include <cstddef>

constexpr int B_ = 16, N_ = 2048, D_ = 64;
constexpr size_t ND = (size_t)N_ * D_;
constexpr size_t N2 = (size_t)N_ * N_;
// fragment-tiled P: tile (qt,kt) = 128q x 64k = 8192 floats
// idx = w*1024 + (mt*4+nt)*128 + lane*4 + e
constexpr int TILE = 8192;

// ---- scratch (__device__ globals; no allocations allowed) ----
__device__ float g_P[(size_t)B_ * N2];        // fragment-tiled exp(scores)
__device__ float g_rdenom[N2];                // fragment-tiled
__device__ uint4 g_QFh[262144];               // Q bf16-hi in A-fragment layout, 4MB
__device__ uint4 g_QFl[262144];               // Q bf16-lo
__device__ __nv_bfloat16 g_Kh[(size_t)B_ * ND];
__device__ __nv_bfloat16 g_Kl[(size_t)B_ * ND];
__device__ __nv_bfloat16 g_Vth[(size_t)B_ * ND];  // [b][d][k]
__device__ __nv_bfloat16 g_Vtl[(size_t)B_ * ND];

#define SW128(o) ((o) ^ (((o) >> 3) & 0x70))

__device__ __forceinline__ uint32_t smem_u32(const void* p) {
    uint32_t a;
    asm("{ .reg .u64 t; cvta.to.shared.u64 t, %1; cvt.u32.u64 %0, t; }" : "=r"(a) : "l"(p));
    return a;
}
__device__ __forceinline__ void ldmx4(uint32_t* r, uint32_t addr) {
    asm volatile("ldmatrix.sync.aligned.m8n8.x4.shared.b16 {%0,%1,%2,%3}, [%4];"
                 : "=r"(r[0]), "=r"(r[1]), "=r"(r[2]), "=r"(r[3]) : "r"(addr));
}
__device__ __forceinline__ void mma16816(float* d, const uint32_t* a, uint32_t b0, uint32_t b1) {
    asm volatile(
        "mma.sync.aligned.m16n8k16.row.col.f32.bf16.bf16.f32 "
        "{%0,%1,%2,%3}, {%4,%5,%6,%7}, {%8,%9}, {%0,%1,%2,%3};"
        : "+f"(d[0]), "+f"(d[1]), "+f"(d[2]), "+f"(d[3])
        : "r"(a[0]), "r"(a[1]), "r"(a[2]), "r"(a[3]), "r"(b0), "r"(b1));
}
__device__ __forceinline__ void split2(float a, float b, uint32_t& h, uint32_t& l) {
    __nv_bfloat16 ha = __float2bfloat16(a), hb = __float2bfloat16(b);
    float la = a - __bfloat162float(ha), lb = b - __bfloat162float(hb);
    __nv_bfloat16 lae = __float2bfloat16(la), lbe = __float2bfloat16(lb);
    h = (uint32_t)__bfloat16_as_ushort(ha) | ((uint32_t)__bfloat16_as_ushort(hb) << 16);
    l = (uint32_t)__bfloat16_as_ushort(lae) | ((uint32_t)__bfloat16_as_ushort(lbe) << 16);
}
__device__ __forceinline__ void cp16(uint32_t dst, const void* src) {
    asm volatile("cp.async.cg.shared.global [%0], [%1], 16;" :: "r"(dst), "l"(src));
}
__device__ __forceinline__ void cp_commit() {
    asm volatile("cp.async.commit_group;" ::: "memory");
}

// ===========================================================================
// k0_prep (merged): flat grid of 2560 blocks x 256 thr
//   [0,1024):    K split (fp32 -> bf16 hi/lo, row-major)
//   [1024,1536): V transpose+split -> Vt [b][d][k]
//   [1536,2560): Q -> A-fragment layout (bf16 hi/lo), scale folded
// ===========================================================================
__global__ __launch_bounds__(256) void k0_prep(const float* __restrict__ Q,
                                               const float* __restrict__ K,
                                               const float* __restrict__ V) {
    __shared__ float smv[64][65];
    const int bid = blockIdx.x;
    const int t = threadIdx.x;

    if (bid < 1024) {
        // ---- K split ----
        size_t i = (size_t)bid * 256 + t;   // unit of 8 floats
        float4 a = ((const float4*)K)[i * 2];
        float4 b = ((const float4*)K)[i * 2 + 1];
        uint32_t h[4], l[4];
        split2(a.x, a.y, h[0], l[0]);
        split2(a.z, a.w, h[1], l[1]);
        split2(b.x, b.y, h[2], l[2]);
        split2(b.z, b.w, h[3], l[3]);
        ((uint4*)g_Kh)[i] = make_uint4(h[0], h[1], h[2], h[3]);
        ((uint4*)g_Kl)[i] = make_uint4(l[0], l[1], l[2], l[3]);
    } else if (bid < 1536) {
        // ---- V transpose + split ----
        const int v = bid - 1024;
        const int b = v >> 5, k0 = (v & 31) * 64;
        const float* Vb = V + ((size_t)b * N_ + k0) * D_;
#pragma unroll
        for (int it = 0; it < 4; it++) {
            int f = t + it * 256;
            int k = f >> 4, d4 = f & 15;
            float4 vv = *(const float4*)(Vb + k * D_ + d4 * 4);
            smv[k][d4 * 4 + 0] = vv.x;
            smv[k][d4 * 4 + 1] = vv.y;
            smv[k][d4 * 4 + 2] = vv.z;
            smv[k][d4 * 4 + 3] = vv.w;
        }
        __syncthreads();
        const int d = t >> 2, kg = t & 3;
        uint32_t h[8], l[8];
#pragma unroll
        for (int j = 0; j < 8; j++)
            split2(smv[kg * 16 + j * 2][d], smv[kg * 16 + j * 2 + 1][d], h[j], l[j]);
        size_t off = ((size_t)b * D_ + d) * N_ + k0 + kg * 16;
        *(uint4*)(g_Vth + off)     = make_uint4(h[0], h[1], h[2], h[3]);
        *(uint4*)(g_Vth + off + 8) = make_uint4(h[4], h[5], h[6], h[7]);
        *(uint4*)(g_Vtl + off)     = make_uint4(l[0], l[1], l[2], l[3]);
        *(uint4*)(g_Vtl + off + 8) = make_uint4(l[4], l[5], l[6], l[7]);
    } else {
        // ---- Q -> A-fragment layout ----
        // wg in [0,8192): ks = wg&3, rg = (wg>>2)&127, b = wg>>9
        const int lane = t & 31;
        const int wg = (bid - 1536) * 8 + (t >> 5);
        const int ks = wg & 3, rg = (wg >> 2) & 127, b = wg >> 9;
        const int row0 = rg * 16 + (lane >> 2);
        const int c0 = ks * 16 + (lane & 3) * 2;
        const float* Qb = Q + ((size_t)b * N_ + row0) * D_;
        float2 v00 = *(const float2*)(Qb + c0);            // a0: row0, c0..c0+1
        float2 v10 = *(const float2*)(Qb + 8 * D_ + c0);   // a1: row0+8
        float2 v02 = *(const float2*)(Qb + c0 + 8);        // a2: row0, c0+8..9
        float2 v12 = *(const float2*)(Qb + 8 * D_ + c0 + 8);
        const float s = 0.125f;
        uint32_t h0, l0, h1, l1, h2, l2, h3, l3;
        split2(v00.x * s, v00.y * s, h0, l0);
        split2(v10.x * s, v10.y * s, h1, l1);
        split2(v02.x * s, v02.y * s, h2, l2);
        split2(v12.x * s, v12.y * s, h3, l3);
        g_QFh[wg * 32 + lane] = make_uint4(h0, h1, h2, h3);
        g_QFl[wg * 32 + lane] = make_uint4(l0, l1, l2, l3);
    }
}

// ===========================================================================
// k1: scores. 256 thr, tile 128q x 64k, warp 32q x 32k.
// A (Q) fragments: direct coalesced LDG from g_QFh/g_QFl (L2-resident).
// B (K): cp.async double-buffered smem + ldmatrix, hoisted swizzle offsets.
// P/rdenom written fragment-tiled (coalesced STG.128).
// smem: 2 buffers x (Kh 8KB @+0, Kl 8KB @+8192) = 32KB
// ===========================================================================
__device__ __forceinline__ void k1_stage(uint32_t buf, int tid, size_t kbase) {
#pragma unroll
    for (int it = 0; it < 2; it++) {
        int u = tid + it * 256;
        int k = u >> 3, g = u & 7;
        uint32_t dst = buf + SW128((uint32_t)(k * 128 + g * 16));
        cp16(dst,        g_Kh + kbase + k * D_ + g * 8);
        cp16(dst + 8192, g_Kl + kbase + k * D_ + g * 8);
    }
    cp_commit();
}

__global__ __launch_bounds__(256, 2) void k1_scores() {
    extern __shared__ __align__(128) uint8_t smem[];   // 32768
    const uint32_t sb = smem_u32(smem);
    const int tid = threadIdx.x;
    const int lane = tid & 31, w = tid >> 5;
    const int kt = blockIdx.x, qt = blockIdx.y;
    const int k0 = kt * 64;
    const int wq = w >> 1, wk = w & 1;
    const int fragoff = w * 1024 + lane * 4;

    // hoisted K-side ldmatrix offsets (buffer-relative), b-invariant
    uint32_t koff[2][4];
    {
        const int brow = wk * 32 + (lane & 15);
        const int bcol = (lane >> 4) * 16;
#pragma unroll
        for (int np = 0; np < 2; np++)
#pragma unroll
            for (int ks = 0; ks < 4; ks++)
                koff[np][ks] = SW128((uint32_t)((brow + np * 16) * 128 + ks * 32 + bcol));
    }
    // A fragment base (uint4 index): rg = qt*8 + wq*2 (+mt), ks fastest
    const size_t arg0 = (size_t)(qt * 8 + wq * 2) * 4;

    float denom[2][4][4];
#pragma unroll
    for (int mt = 0; mt < 2; mt++)
#pragma unroll
        for (int nt = 0; nt < 4; nt++)
#pragma unroll
            for (int r = 0; r < 4; r++) denom[mt][nt][r] = 0.0f;

    k1_stage(sb,         tid, (size_t)0 * ND + (size_t)k0 * D_);
    k1_stage(sb + 16384, tid, (size_t)1 * ND + (size_t)k0 * D_);

    for (int b = 0; b < B_; b++) {
        const uint32_t buf = sb + (b & 1) * 16384;
        if (b < B_ - 1) asm volatile("cp.async.wait_group 1;" ::: "memory");
        else            asm volatile("cp.async.wait_group 0;" ::: "memory");
        __syncthreads();

        float Dc[2][4][4];
#pragma unroll
        for (int mt = 0; mt < 2; mt++)
#pragma unroll
            for (int nt = 0; nt < 4; nt++)
#pragma unroll
                for (int r = 0; r < 4; r++) Dc[mt][nt][r] = 0.0f;

        const size_t ab = (size_t)b * 512 + arg0;   // uint4-slab index base
#pragma unroll
        for (int ks = 0; ks < 4; ks++) {
            uint4 aH0 = g_QFh[(ab + ks) * 32 + lane];
            uint4 aH1 = g_QFh[(ab + 4 + ks) * 32 + lane];
            uint4 aL0 = g_QFl[(ab + ks) * 32 + lane];
            uint4 aL1 = g_QFl[(ab + 4 + ks) * 32 + lane];
            uint32_t bH[2][4], bL[2][4];
            ldmx4(bH[0], buf + koff[0][ks]);
            ldmx4(bH[1], buf + koff[1][ks]);
#pragma unroll
            for (int np = 0; np < 2; np++) {
                mma16816(Dc[0][np * 2],     (const uint32_t*)&aH0, bH[np][0], bH[np][2]);
                mma16816(Dc[0][np * 2 + 1], (const uint32_t*)&aH0, bH[np][1], bH[np][3]);
                mma16816(Dc[1][np * 2],     (const uint32_t*)&aH1, bH[np][0], bH[np][2]);
                mma16816(Dc[1][np * 2 + 1], (const uint32_t*)&aH1, bH[np][1], bH[np][3]);
            }
#pragma unroll
            for (int np = 0; np < 2; np++) {
                mma16816(Dc[0][np * 2],     (const uint32_t*)&aL0, bH[np][0], bH[np][2]);
                mma16816(Dc[0][np * 2 + 1], (const uint32_t*)&aL0, bH[np][1], bH[np][3]);
                mma16816(Dc[1][np * 2],     (const uint32_t*)&aL1, bH[np][0], bH[np][2]);
                mma16816(Dc[1][np * 2 + 1], (const uint32_t*)&aL1, bH[np][1], bH[np][3]);
            }
            ldmx4(bL[0], buf + 8192 + koff[0][ks]);
            ldmx4(bL[1], buf + 8192 + koff[1][ks]);
#pragma unroll
            for (int np = 0; np < 2; np++) {
                mma16816(Dc[0][np * 2],     (const uint32_t*)&aH0, bL[np][0], bL[np][2]);
                mma16816(Dc[0][np * 2 + 1], (const uint32_t*)&aH0, bL[np][1], bL[np][3]);
                mma16816(Dc[1][np * 2],     (const uint32_t*)&aH1, bL[np][0], bL[np][2]);
                mma16816(Dc[1][np * 2 + 1], (const uint32_t*)&aH1, bL[np][1], bL[np][3]);
            }
        }

        // ---- exp + denom + fragment-tiled coalesced P store ----
        float* Pb = g_P + (((size_t)b * 16 + qt) * 32 + kt) * TILE + fragoff;
#pragma unroll
        for (int mt = 0; mt < 2; mt++)
#pragma unroll
            for (int nt = 0; nt < 4; nt++) {
                float e0 = __expf(Dc[mt][nt][0]);
                float e1 = __expf(Dc[mt][nt][1]);
                float e2 = __expf(Dc[mt][nt][2]);
                float e3 = __expf(Dc[mt][nt][3]);
                denom[mt][nt][0] += e0; denom[mt][nt][1] += e1;
                denom[mt][nt][2] += e2; denom[mt][nt][3] += e3;
                *(float4*)(Pb + (mt * 4 + nt) * 128) = make_float4(e0, e1, e2, e3);
            }
        __syncthreads();
        if (b + 2 < B_)
            k1_stage(buf, tid, (size_t)(b + 2) * ND + (size_t)k0 * D_);
    }

    // ---- rdenom (fragment-tiled, coalesced) ----
    float* Rb = g_rdenom + ((size_t)qt * 32 + kt) * TILE + fragoff;
#pragma unroll
    for (int mt = 0; mt < 2; mt++)
#pragma unroll
        for (int nt = 0; nt < 4; nt++)
            *(float4*)(Rb + (mt * 4 + nt) * 128) = make_float4(
                1.0f / denom[mt][nt][0], 1.0f / denom[mt][nt][1],
                1.0f / denom[mt][nt][2], 1.0f / denom[mt][nt][3]);
}

// ===========================================================================
// k2: out[b] = (P[b]*rdenom) @ V[b]. Block (b, qt), 256 thr.
// A-fragments: coalesced LDG from fragment-tiled g_P/g_rdenom (no smem/ldsm).
// V double-buffered via cp.async; swizzle offsets hoisted.
// ===========================================================================
__device__ __forceinline__ void k2_stageB(uint32_t buf, int tid, size_t vbase) {
#pragma unroll
    for (int it = 0; it < 2; it++) {
        int u = tid + it * 256;
        int d = u >> 3, g = u & 7;
        uint32_t dst = buf + SW128((uint32_t)(d * 128 + g * 16));
        cp16(dst,        g_Vth + vbase + (size_t)d * N_ + g * 8);
        cp16(dst + 8192, g_Vtl + vbase + (size_t)d * N_ + g * 8);
    }
    cp_commit();
}

__global__ __launch_bounds__(256, 2) void k2_out(float* __restrict__ O) {
    extern __shared__ __align__(128) uint8_t smem[];   // 32768
    const uint32_t sb = smem_u32(smem);
    const int tid = threadIdx.x;
    const int lane = tid & 31, w = tid >> 5;
    const int b = blockIdx.x, qt = blockIdx.y;
    const int wq2 = w >> 1, kh = w & 1;
    const int fragoff = w * 1024 + lane * 4;
    const size_t vb0 = (size_t)b * ND;

    // hoisted V-side ldmatrix offsets (buffer-relative), c-invariant
    uint32_t voff[2][4];
#pragma unroll
    for (int kg = 0; kg < 2; kg++)
#pragma unroll
        for (int g16 = 0; g16 < 4; g16++)
            voff[kg][g16] = SW128((uint32_t)((g16 * 16 + (lane & 15)) * 128 +
                                             kh * 64 + kg * 32 + (lane >> 4) * 16));

    float Dc[2][8][4];
#pragma unroll
    for (int mt = 0; mt < 2; mt++)
#pragma unroll
        for (int j = 0; j < 8; j++)
#pragma unroll
            for (int r = 0; r < 4; r++) Dc[mt][j][r] = 0.0f;

    k2_stageB(sb, tid, vb0);   // chunk 0 -> buffer 0

    for (int c = 0; c < 32; c++) {
        const uint32_t buf = sb + (c & 1) * 16384;
        if (c + 1 < 32) {
            k2_stageB(sb + ((c + 1) & 1) * 16384, tid, vb0 + (c + 1) * 64);
            asm volatile("cp.async.wait_group 1;" ::: "memory");
        } else {
            asm volatile("cp.async.wait_group 0;" ::: "memory");
        }
        __syncthreads();

        const float* pA = g_P + (((size_t)b * 16 + qt) * 32 + c) * TILE + fragoff;
        const float* pR = g_rdenom + ((size_t)qt * 32 + c) * TILE + fragoff;

#pragma unroll
        for (int kg = 0; kg < 2; kg++) {
            uint32_t aH[2][4], aL[2][4];
#pragma unroll
            for (int mt = 0; mt < 2; mt++)
#pragma unroll
                for (int hf = 0; hf < 2; hf++) {
                    int i = mt * 4 + kg * 2 + hf;
                    float4 p = *(const float4*)(pA + i * 128);
                    float4 r = *(const float4*)(pR + i * 128);
                    uint32_t h01, l01, h23, l23;
                    split2(p.x * r.x, p.y * r.y, h01, l01);
                    split2(p.z * r.z, p.w * r.w, h23, l23);
                    aH[mt][hf * 2] = h01; aH[mt][hf * 2 + 1] = h23;
                    aL[mt][hf * 2] = l01; aL[mt][hf * 2 + 1] = l23;
                }
#pragma unroll
            for (int g16 = 0; g16 < 4; g16++) {
                uint32_t bh[4], bl[4];
                ldmx4(bh, buf + voff[kg][g16]);
                ldmx4(bl, buf + 8192 + voff[kg][g16]);
#pragma unroll
                for (int mt = 0; mt < 2; mt++) {
                    mma16816(Dc[mt][g16 * 2],     aH[mt], bh[0], bh[2]);
                    mma16816(Dc[mt][g16 * 2 + 1], aH[mt], bh[1], bh[3]);
                    mma16816(Dc[mt][g16 * 2],     aL[mt], bh[0], bh[2]);
                    mma16816(Dc[mt][g16 * 2 + 1], aL[mt], bh[1], bh[3]);
                    mma16816(Dc[mt][g16 * 2],     aH[mt], bl[0], bl[2]);
                    mma16816(Dc[mt][g16 * 2 + 1], aH[mt], bl[1], bl[3]);
                }
            }
        }
        __syncthreads();
    }

    // ---- cross-warp (kh) reduction via smem, then O store ----
    if (kh == 1) {
#pragma unroll
        for (int mt = 0; mt < 2; mt++)
#pragma unroll
            for (int j = 0; j < 8; j++)
                *(float4*)(smem + wq2 * 8192 + (mt * 8 + j) * 512 + lane * 16) =
                    make_float4(Dc[mt][j][0], Dc[mt][j][1], Dc[mt][j][2], Dc[mt][j][3]);
    }
    __syncthreads();
    if (kh == 0) {
#pragma unroll
        for (int mt = 0; mt < 2; mt++) {
            int r0 = qt * 128 + wq2 * 32 + mt * 16 + (lane >> 2);
#pragma unroll
            for (int j = 0; j < 8; j++) {
                float4 o = *(float4*)(smem + wq2 * 8192 + (mt * 8 + j) * 512 + lane * 16);
                float v0 = Dc[mt][j][0] + o.x;
                float v1 = Dc[mt][j][1] + o.y;
                float v2 = Dc[mt][j][2] + o.z;
                float v3 = Dc[mt][j][3] + o.w;
                int cc = j * 8 + 2 * (lane & 3);
                *(float2*)(O + ((size_t)b * N_ + r0) * D_ + cc)     = make_float2(v0, v1);
                *(float2*)(O + ((size_t)b * N_ + r0 + 8) * D_ + cc) = make_float2(v2, v3);
            }
        }
    }
}

// ===========================================================================
extern "C" void kernel_launch(void* const* d_in, const int* in_sizes, int n_in,
                              void* d_out, int out_size) {
    const float* Q = (const float*)d_in[0];
    const float* K = (const float*)d_in[1];
    const float* V = (const float*)d_in[2];
    float* O = (float*)d_out;

    cudaFuncSetAttribute(k1_scores, cudaFuncAttributeMaxDynamicSharedMemorySize, 32768);
    cudaFuncSetAttribute(k2_out, cudaFuncAttributeMaxDynamicSharedMemorySize, 32768);

    k0_prep<<<2560, 256>>>(Q, K, V);
    k1_scores<<<dim3(N_ / 64, N_ / 128), 256, 32768>>>();   // (kt, qt)
    k2_out<<<dim3(B_, N_ / 128), 256, 32768>>>(O);          // (b, qt)
}

// round 11
// speedup vs baseline: 1.1461x; 1.1461x over previous
#include <cuda_runtime.h>
#include <cuda_bf16.h>
#include <cstdint>
#include <cstddef>

constexpr int B_ = 16, N_ = 2048, D_ = 64;
constexpr size_t ND = (size_t)N_ * D_;
constexpr size_t N2 = (size_t)N_ * N_;
// fragment-tiled P: tile (qt,kt) = 128q x 64k = 8192 floats
// idx = w*1024 + (mt*4+nt)*128 + lane*4 + e
constexpr int TILE = 8192;

// ---- scratch (__device__ globals; no allocations allowed) ----
__device__ float g_P[(size_t)B_ * N2];        // fragment-tiled exp(scores)
__device__ float g_rdenom[N2];                // fragment-tiled
__device__ __nv_bfloat16 g_Qh[(size_t)B_ * ND];
__device__ __nv_bfloat16 g_Ql[(size_t)B_ * ND];
__device__ __nv_bfloat16 g_Kh[(size_t)B_ * ND];
__device__ __nv_bfloat16 g_Kl[(size_t)B_ * ND];
// V in B-fragment layout: slot = ((b*32 + c)*16 + kh*8 + kg*4 + g16),
// entry [slot*32 + lane] = uint4(t0,t1,t2,t3) per ldmatrix x4 mapping.
__device__ uint4 g_VFh[262144];               // 4MB
__device__ uint4 g_VFl[262144];               // 4MB

#define SW128(o) ((o) ^ (((o) >> 3) & 0x70))

__device__ __forceinline__ uint32_t smem_u32(const void* p) {
    uint32_t a;
    asm("{ .reg .u64 t; cvta.to.shared.u64 t, %1; cvt.u32.u64 %0, t; }" : "=r"(a) : "l"(p));
    return a;
}
__device__ __forceinline__ void ldmx4(uint32_t* r, uint32_t addr) {
    asm volatile("ldmatrix.sync.aligned.m8n8.x4.shared.b16 {%0,%1,%2,%3}, [%4];"
                 : "=r"(r[0]), "=r"(r[1]), "=r"(r[2]), "=r"(r[3]) : "r"(addr));
}
__device__ __forceinline__ void mma16816(float* d, const uint32_t* a, uint32_t b0, uint32_t b1) {
    asm volatile(
        "mma.sync.aligned.m16n8k16.row.col.f32.bf16.bf16.f32 "
        "{%0,%1,%2,%3}, {%4,%5,%6,%7}, {%8,%9}, {%0,%1,%2,%3};"
        : "+f"(d[0]), "+f"(d[1]), "+f"(d[2]), "+f"(d[3])
        : "r"(a[0]), "r"(a[1]), "r"(a[2]), "r"(a[3]), "r"(b0), "r"(b1));
}
__device__ __forceinline__ void split2(float a, float b, uint32_t& h, uint32_t& l) {
    __nv_bfloat16 ha = __float2bfloat16(a), hb = __float2bfloat16(b);
    float la = a - __bfloat162float(ha), lb = b - __bfloat162float(hb);
    __nv_bfloat16 lae = __float2bfloat16(la), lbe = __float2bfloat16(lb);
    h = (uint32_t)__bfloat16_as_ushort(ha) | ((uint32_t)__bfloat16_as_ushort(hb) << 16);
    l = (uint32_t)__bfloat16_as_ushort(lae) | ((uint32_t)__bfloat16_as_ushort(lbe) << 16);
}
__device__ __forceinline__ void cp16(uint32_t dst, const void* src) {
    asm volatile("cp.async.cg.shared.global [%0], [%1], 16;" :: "r"(dst), "l"(src));
}
__device__ __forceinline__ void cp_commit() {
    asm volatile("cp.async.commit_group;" ::: "memory");
}

// ===========================================================================
// k0_prep (merged): flat grid of 2560 blocks x 256 thr
//   [0,1024):    K split (fp32 -> bf16 hi/lo, row-major)
//   [1024,1536): V -> B-fragment layout (bf16 hi/lo) via smem tile
//   [1536,2560): Q split (row-major, scale folded)
// ===========================================================================
__global__ __launch_bounds__(256) void k0_prep(const float* __restrict__ Q,
                                               const float* __restrict__ K,
                                               const float* __restrict__ V) {
    __shared__ float smv[64][65];
    const int bid = blockIdx.x;
    const int t = threadIdx.x;

    if (bid < 1024) {
        // ---- K split ----
        size_t i = (size_t)bid * 256 + t;   // unit of 8 floats
        float4 a = ((const float4*)K)[i * 2];
        float4 b = ((const float4*)K)[i * 2 + 1];
        uint32_t h[4], l[4];
        split2(a.x, a.y, h[0], l[0]);
        split2(a.z, a.w, h[1], l[1]);
        split2(b.x, b.y, h[2], l[2]);
        split2(b.z, b.w, h[3], l[3]);
        ((uint4*)g_Kh)[i] = make_uint4(h[0], h[1], h[2], h[3]);
        ((uint4*)g_Kl)[i] = make_uint4(l[0], l[1], l[2], l[3]);
    } else if (bid < 1536) {
        // ---- V -> B-fragment layout ----
        const int v = bid - 1024;
        const int b = v >> 5, c = v & 31;
        const int k0 = c * 64;
        const float* Vb = V + ((size_t)b * N_ + k0) * D_;
#pragma unroll
        for (int it = 0; it < 4; it++) {
            int f = t + it * 256;
            int k = f >> 4, d4 = f & 15;
            float4 vv = *(const float4*)(Vb + k * D_ + d4 * 4);
            smv[k][d4 * 4 + 0] = vv.x;
            smv[k][d4 * 4 + 1] = vv.y;
            smv[k][d4 * 4 + 2] = vv.z;
            smv[k][d4 * 4 + 3] = vv.w;
        }
        __syncthreads();
        const int lane = t & 31;
        const int wslot = t >> 5;   // 0..7, 2 slots each
#pragma unroll
        for (int r = 0; r < 2; r++) {
            int s = wslot * 2 + r;                      // 0..15
            int kh = s >> 3, kg = (s >> 2) & 1, g16 = s & 3;
            int d0 = g16 * 16, kl0 = kh * 32 + kg * 16;
            uint32_t h[4], l[4];
#pragma unroll
            for (int i = 0; i < 4; i++) {
                int d = d0 + (i & 1) * 8 + (lane >> 2);
                int kk = kl0 + (i >> 1) * 8 + (lane & 3) * 2;
                split2(smv[kk][d], smv[kk + 1][d], h[i], l[i]);
            }
            size_t slot = ((size_t)(b * 32 + c) * 16 + s) * 32 + lane;
            g_VFh[slot] = make_uint4(h[0], h[1], h[2], h[3]);
            g_VFl[slot] = make_uint4(l[0], l[1], l[2], l[3]);
        }
    } else {
        // ---- Q split (scale folded) ----
        size_t i = (size_t)(bid - 1536) * 256 + t;
        float4 a = ((const float4*)Q)[i * 2];
        float4 b = ((const float4*)Q)[i * 2 + 1];
        const float s = 0.125f;
        uint32_t h[4], l[4];
        split2(a.x * s, a.y * s, h[0], l[0]);
        split2(a.z * s, a.w * s, h[1], l[1]);
        split2(b.x * s, b.y * s, h[2], l[2]);
        split2(b.z * s, b.w * s, h[3], l[3]);
        ((uint4*)g_Qh)[i] = make_uint4(h[0], h[1], h[2], h[3]);
        ((uint4*)g_Ql)[i] = make_uint4(l[0], l[1], l[2], l[3]);
    }
}

// ---------------------------------------------------------------------------
// Shared-fragment 3-split MMA phase for k1 (round-9 proven).
// Buffer: Qh@+0 (16K), Ql@+16384, Kh@+32768 (8K), Kl@+40960
// ---------------------------------------------------------------------------
__device__ __forceinline__ void mma_phase(uint32_t buf, float Dc[2][4][4],
                                          int arow, int brow, int acol) {
#pragma unroll
    for (int ks = 0; ks < 4; ks++) {
        uint32_t aH[2][4], bH[2][4];
#pragma unroll
        for (int mt = 0; mt < 2; mt++)
            ldmx4(aH[mt], buf + SW128((uint32_t)((arow + mt * 16) * 128 + ks * 32 + acol)));
#pragma unroll
        for (int np = 0; np < 2; np++)
            ldmx4(bH[np], buf + 32768 + SW128((uint32_t)((brow + np * 16) * 128 + ks * 32 + acol)));
#pragma unroll
        for (int mt = 0; mt < 2; mt++)
#pragma unroll
            for (int np = 0; np < 2; np++) {
                mma16816(Dc[mt][np * 2],     aH[mt], bH[np][0], bH[np][2]);
                mma16816(Dc[mt][np * 2 + 1], aH[mt], bH[np][1], bH[np][3]);
            }
        {   // Al * Bh
            uint32_t aL[2][4];
#pragma unroll
            for (int mt = 0; mt < 2; mt++)
                ldmx4(aL[mt], buf + 16384 + SW128((uint32_t)((arow + mt * 16) * 128 + ks * 32 + acol)));
#pragma unroll
            for (int mt = 0; mt < 2; mt++)
#pragma unroll
                for (int np = 0; np < 2; np++) {
                    mma16816(Dc[mt][np * 2],     aL[mt], bH[np][0], bH[np][2]);
                    mma16816(Dc[mt][np * 2 + 1], aL[mt], bH[np][1], bH[np][3]);
                }
        }
        {   // Ah * Bl
            uint32_t bL[2][4];
#pragma unroll
            for (int np = 0; np < 2; np++)
                ldmx4(bL[np], buf + 40960 + SW128((uint32_t)((brow + np * 16) * 128 + ks * 32 + acol)));
#pragma unroll
            for (int mt = 0; mt < 2; mt++)
#pragma unroll
                for (int np = 0; np < 2; np++) {
                    mma16816(Dc[mt][np * 2],     aH[mt], bL[np][0], bL[np][2]);
                    mma16816(Dc[mt][np * 2 + 1], aH[mt], bL[np][1], bL[np][3]);
                }
        }
    }
}

// ===========================================================================
// k1: scores (round-9 proven). Double-buffered cp.async staging of Q+K;
// P/rdenom stored fragment-tiled (coalesced STG.128).
// ===========================================================================
__device__ __forceinline__ void k1_stage(uint32_t buf, int tid, size_t qbase, size_t kbase) {
#pragma unroll
    for (int it = 0; it < 4; it++) {
        int u = tid + it * 256;
        int q = u >> 3, g = u & 7;
        uint32_t dst = buf + SW128((uint32_t)(q * 128 + g * 16));
        cp16(dst,         g_Qh + qbase + q * D_ + g * 8);
        cp16(dst + 16384, g_Ql + qbase + q * D_ + g * 8);
    }
#pragma unroll
    for (int it = 0; it < 2; it++) {
        int u = tid + it * 256;
        int k = u >> 3, g = u & 7;
        uint32_t dst = buf + 32768 + SW128((uint32_t)(k * 128 + g * 16));
        cp16(dst,        g_Kh + kbase + k * D_ + g * 8);
        cp16(dst + 8192, g_Kl + kbase + k * D_ + g * 8);
    }
    cp_commit();
}

__global__ __launch_bounds__(256, 2) void k1_scores() {
    extern __shared__ __align__(128) uint8_t smem[];   // 98304
    const uint32_t sb = smem_u32(smem);
    const int tid = threadIdx.x;
    const int lane = tid & 31, w = tid >> 5;
    const int kt = blockIdx.x, qt = blockIdx.y;
    const int q0 = qt * 128, k0 = kt * 64;
    const int wq = w >> 1, wk = w & 1;
    const int arow = wq * 32 + (lane & 15);
    const int brow = wk * 32 + (lane & 15);
    const int acol = (lane >> 4) * 16;
    const int fragoff = w * 1024 + lane * 4;

    float denom[2][4][4];
#pragma unroll
    for (int mt = 0; mt < 2; mt++)
#pragma unroll
        for (int nt = 0; nt < 4; nt++)
#pragma unroll
            for (int r = 0; r < 4; r++) denom[mt][nt][r] = 0.0f;

    k1_stage(sb,         tid, (size_t)0 * ND + (size_t)q0 * D_, (size_t)0 * ND + (size_t)k0 * D_);
    k1_stage(sb + 49152, tid, (size_t)1 * ND + (size_t)q0 * D_, (size_t)1 * ND + (size_t)k0 * D_);

    for (int b = 0; b < B_; b++) {
        const uint32_t buf = sb + (b & 1) * 49152;
        if (b < B_ - 1) asm volatile("cp.async.wait_group 1;" ::: "memory");
        else            asm volatile("cp.async.wait_group 0;" ::: "memory");
        __syncthreads();

        float Dc[2][4][4];
#pragma unroll
        for (int mt = 0; mt < 2; mt++)
#pragma unroll
            for (int nt = 0; nt < 4; nt++)
#pragma unroll
                for (int r = 0; r < 4; r++) Dc[mt][nt][r] = 0.0f;

        mma_phase(buf, Dc, arow, brow, acol);

        // ---- exp + denom + fragment-tiled coalesced P store ----
        float* Pb = g_P + (((size_t)b * 16 + qt) * 32 + kt) * TILE + fragoff;
#pragma unroll
        for (int mt = 0; mt < 2; mt++)
#pragma unroll
            for (int nt = 0; nt < 4; nt++) {
                float e0 = __expf(Dc[mt][nt][0]);
                float e1 = __expf(Dc[mt][nt][1]);
                float e2 = __expf(Dc[mt][nt][2]);
                float e3 = __expf(Dc[mt][nt][3]);
                denom[mt][nt][0] += e0; denom[mt][nt][1] += e1;
                denom[mt][nt][2] += e2; denom[mt][nt][3] += e3;
                *(float4*)(Pb + (mt * 4 + nt) * 128) = make_float4(e0, e1, e2, e3);
            }
        __syncthreads();
        if (b + 2 < B_)
            k1_stage(buf, tid, (size_t)(b + 2) * ND + (size_t)q0 * D_,
                               (size_t)(b + 2) * ND + (size_t)k0 * D_);
    }

    // ---- rdenom (fragment-tiled, coalesced) ----
    float* Rb = g_rdenom + ((size_t)qt * 32 + kt) * TILE + fragoff;
#pragma unroll
    for (int mt = 0; mt < 2; mt++)
#pragma unroll
        for (int nt = 0; nt < 4; nt++)
            *(float4*)(Rb + (mt * 4 + nt) * 128) = make_float4(
                1.0f / denom[mt][nt][0], 1.0f / denom[mt][nt][1],
                1.0f / denom[mt][nt][2], 1.0f / denom[mt][nt][3]);
}

// ===========================================================================
// k2: out[b] = (P[b]*rdenom) @ V[b]. Block (b, qt), 256 thr.
// ALL operands via coalesced LDG (A from fragment-tiled g_P/g_rdenom,
// B from B-fragment g_VFh/g_VFl). No smem / no syncthreads in the main
// loop -> warps free-run, memory and MMA phases interleave across warps.
// ===========================================================================
__global__ __launch_bounds__(256, 2) void k2_out(float* __restrict__ O) {
    __shared__ __align__(16) float red[8192];   // 32KB, epilogue only
    const int tid = threadIdx.x;
    const int lane = tid & 31, w = tid >> 5;
    const int b = blockIdx.x, qt = blockIdx.y;
    const int wq2 = w >> 1, kh = w & 1;
    const int fragoff = w * 1024 + lane * 4;

    float Dc[2][8][4];
#pragma unroll
    for (int mt = 0; mt < 2; mt++)
#pragma unroll
        for (int j = 0; j < 8; j++)
#pragma unroll
            for (int r = 0; r < 4; r++) Dc[mt][j][r] = 0.0f;

    for (int c = 0; c < 32; c++) {
        const float* pA = g_P + (((size_t)b * 16 + qt) * 32 + c) * TILE + fragoff;
        const float* pR = g_rdenom + ((size_t)qt * 32 + c) * TILE + fragoff;
        const size_t vbase = ((size_t)(b * 32 + c) * 16 + kh * 8) * 32 + lane;

#pragma unroll
        for (int kg = 0; kg < 2; kg++) {
            uint32_t aH[2][4], aL[2][4];
#pragma unroll
            for (int mt = 0; mt < 2; mt++)
#pragma unroll
                for (int hf = 0; hf < 2; hf++) {
                    int i = mt * 4 + kg * 2 + hf;
                    float4 p = *(const float4*)(pA + i * 128);
                    float4 r = *(const float4*)(pR + i * 128);
                    uint32_t h01, l01, h23, l23;
                    split2(p.x * r.x, p.y * r.y, h01, l01);
                    split2(p.z * r.z, p.w * r.w, h23, l23);
                    aH[mt][hf * 2] = h01; aH[mt][hf * 2 + 1] = h23;
                    aL[mt][hf * 2] = l01; aL[mt][hf * 2 + 1] = l23;
                }
#pragma unroll
            for (int g16 = 0; g16 < 4; g16++) {
                uint4 vh = g_VFh[vbase + (size_t)(kg * 4 + g16) * 32];
                uint4 vl = g_VFl[vbase + (size_t)(kg * 4 + g16) * 32];
#pragma unroll
                for (int mt = 0; mt < 2; mt++) {
                    mma16816(Dc[mt][g16 * 2],     aH[mt], vh.x, vh.z);
                    mma16816(Dc[mt][g16 * 2 + 1], aH[mt], vh.y, vh.w);
                    mma16816(Dc[mt][g16 * 2],     aL[mt], vh.x, vh.z);
                    mma16816(Dc[mt][g16 * 2 + 1], aL[mt], vh.y, vh.w);
                    mma16816(Dc[mt][g16 * 2],     aH[mt], vl.x, vl.z);
                    mma16816(Dc[mt][g16 * 2 + 1], aH[mt], vl.y, vl.w);
                }
            }
        }
    }

    // ---- cross-warp (kh) reduction via smem, then O store ----
    if (kh == 1) {
#pragma unroll
        for (int mt = 0; mt < 2; mt++)
#pragma unroll
            for (int j = 0; j < 8; j++)
                *(float4*)(red + wq2 * 2048 + (mt * 8 + j) * 128 + lane * 4) =
                    make_float4(Dc[mt][j][0], Dc[mt][j][1], Dc[mt][j][2], Dc[mt][j][3]);
    }
    __syncthreads();
    if (kh == 0) {
#pragma unroll
        for (int mt = 0; mt < 2; mt++) {
            int r0 = qt * 128 + wq2 * 32 + mt * 16 + (lane >> 2);
#pragma unroll
            for (int j = 0; j < 8; j++) {
                float4 o = *(float4*)(red + wq2 * 2048 + (mt * 8 + j) * 128 + lane * 4);
                float v0 = Dc[mt][j][0] + o.x;
                float v1 = Dc[mt][j][1] + o.y;
                float v2 = Dc[mt][j][2] + o.z;
                float v3 = Dc[mt][j][3] + o.w;
                int cc = j * 8 + 2 * (lane & 3);
                *(float2*)(O + ((size_t)b * N_ + r0) * D_ + cc)     = make_float2(v0, v1);
                *(float2*)(O + ((size_t)b * N_ + r0 + 8) * D_ + cc) = make_float2(v2, v3);
            }
        }
    }
}

// ===========================================================================
extern "C" void kernel_launch(void* const* d_in, const int* in_sizes, int n_in,
                              void* d_out, int out_size) {
    const float* Q = (const float*)d_in[0];
    const float* K = (const float*)d_in[1];
    const float* V = (const float*)d_in[2];
    float* O = (float*)d_out;

    cudaFuncSetAttribute(k1_scores, cudaFuncAttributeMaxDynamicSharedMemorySize, 98304);

    k0_prep<<<2560, 256>>>(Q, K, V);
    k1_scores<<<dim3(N_ / 64, N_ / 128), 256, 98304>>>();   // (kt, qt)
    k2_out<<<dim3(B_, N_ / 128), 256>>>(O);                 // (b, qt)
}

// round 12
// speedup vs baseline: 1.3889x; 1.2118x over previous
#include <cuda_runtime.h>
#include <cuda_fp16.h>
#include <cstdint>
#include <cstddef>

constexpr int B_ = 16, N_ = 2048, D_ = 64;
constexpr size_t ND = (size_t)N_ * D_;
constexpr size_t N2 = (size_t)N_ * N_;
// fragment-tiled P: tile (qt,kt) = 128q x 64k = 8192 floats
// idx = w*1024 + (mt*4+nt)*128 + lane*4 + e
constexpr int TILE = 8192;

// ---- scratch (__device__ globals; no allocations allowed) ----
__device__ float g_P[(size_t)B_ * N2];        // fragment-tiled exp(scores)
__device__ float g_rdenom[N2];                // fragment-tiled
__device__ __half g_Qh[(size_t)B_ * ND];      // fp16 hi (scale folded)
__device__ __half g_Ql[(size_t)B_ * ND];      // fp16 lo residual
__device__ __half g_Kf[(size_t)B_ * ND];      // fp16 single plane
// V in B-fragment layout (fp16 single plane):
// slot = ((b*32 + c)*16 + kh*8 + kg*4 + g16), entry [slot*32 + lane]
__device__ uint4 g_VFf[262144];               // 4MB

#define SW128(o) ((o) ^ (((o) >> 3) & 0x70))

__device__ __forceinline__ uint32_t smem_u32(const void* p) {
    uint32_t a;
    asm("{ .reg .u64 t; cvta.to.shared.u64 t, %1; cvt.u32.u64 %0, t; }" : "=r"(a) : "l"(p));
    return a;
}
__device__ __forceinline__ void ldmx4(uint32_t* r, uint32_t addr) {
    asm volatile("ldmatrix.sync.aligned.m8n8.x4.shared.b16 {%0,%1,%2,%3}, [%4];"
                 : "=r"(r[0]), "=r"(r[1]), "=r"(r[2]), "=r"(r[3]) : "r"(addr));
}
__device__ __forceinline__ void mma16816(float* d, const uint32_t* a, uint32_t b0, uint32_t b1) {
    asm volatile(
        "mma.sync.aligned.m16n8k16.row.col.f32.f16.f16.f32 "
        "{%0,%1,%2,%3}, {%4,%5,%6,%7}, {%8,%9}, {%0,%1,%2,%3};"
        : "+f"(d[0]), "+f"(d[1]), "+f"(d[2]), "+f"(d[3])
        : "r"(a[0]), "r"(a[1]), "r"(a[2]), "r"(a[3]), "r"(b0), "r"(b1));
}
__device__ __forceinline__ uint32_t pack2h(float a, float b) {
    __half2 v = __floats2half2_rn(a, b);
    return *(uint32_t*)&v;
}
// split into fp16 hi + fp16 lo residual
__device__ __forceinline__ void split2h(float a, float b, uint32_t& h, uint32_t& l) {
    __half ha = __float2half_rn(a), hb = __float2half_rn(b);
    float la = a - __half2float(ha), lb = b - __half2float(hb);
    __half2 hv; hv.x = ha; hv.y = hb;
    __half2 lv; lv.x = __float2half_rn(la); lv.y = __float2half_rn(lb);
    h = *(uint32_t*)&hv;
    l = *(uint32_t*)&lv;
}
__device__ __forceinline__ void cp16(uint32_t dst, const void* src) {
    asm volatile("cp.async.cg.shared.global [%0], [%1], 16;" :: "r"(dst), "l"(src));
}
__device__ __forceinline__ void cp_commit() {
    asm volatile("cp.async.commit_group;" ::: "memory");
}

// ===========================================================================
// k0_prep (merged): flat grid of 2560 blocks x 256 thr
//   [0,1024):    K -> single fp16 plane
//   [1024,1536): V -> B-fragment layout (fp16 single plane) via smem tile
//   [1536,2560): Q -> fp16 hi/lo planes (scale folded)
// ===========================================================================
__global__ __launch_bounds__(256) void k0_prep(const float* __restrict__ Q,
                                               const float* __restrict__ K,
                                               const float* __restrict__ V) {
    __shared__ float smv[64][65];
    const int bid = blockIdx.x;
    const int t = threadIdx.x;

    if (bid < 1024) {
        // ---- K -> fp16 (single plane) ----
        size_t i = (size_t)bid * 256 + t;   // unit of 8 floats
        float4 a = ((const float4*)K)[i * 2];
        float4 b = ((const float4*)K)[i * 2 + 1];
        uint4 o;
        o.x = pack2h(a.x, a.y);
        o.y = pack2h(a.z, a.w);
        o.z = pack2h(b.x, b.y);
        o.w = pack2h(b.z, b.w);
        ((uint4*)g_Kf)[i] = o;
    } else if (bid < 1536) {
        // ---- V -> B-fragment layout (fp16) ----
        const int v = bid - 1024;
        const int b = v >> 5, c = v & 31;
        const int k0 = c * 64;
        const float* Vb = V + ((size_t)b * N_ + k0) * D_;
#pragma unroll
        for (int it = 0; it < 4; it++) {
            int f = t + it * 256;
            int k = f >> 4, d4 = f & 15;
            float4 vv = *(const float4*)(Vb + k * D_ + d4 * 4);
            smv[k][d4 * 4 + 0] = vv.x;
            smv[k][d4 * 4 + 1] = vv.y;
            smv[k][d4 * 4 + 2] = vv.z;
            smv[k][d4 * 4 + 3] = vv.w;
        }
        __syncthreads();
        const int lane = t & 31;
        const int wslot = t >> 5;   // 0..7, 2 slots each
#pragma unroll
        for (int r = 0; r < 2; r++) {
            int s = wslot * 2 + r;                      // 0..15
            int kh = s >> 3, kg = (s >> 2) & 1, g16 = s & 3;
            int d0 = g16 * 16, kl0 = kh * 32 + kg * 16;
            uint32_t h[4];
#pragma unroll
            for (int i = 0; i < 4; i++) {
                int d = d0 + (i & 1) * 8 + (lane >> 2);
                int kk = kl0 + (i >> 1) * 8 + (lane & 3) * 2;
                h[i] = pack2h(smv[kk][d], smv[kk + 1][d]);
            }
            size_t slot = ((size_t)(b * 32 + c) * 16 + s) * 32 + lane;
            g_VFf[slot] = make_uint4(h[0], h[1], h[2], h[3]);
        }
    } else {
        // ---- Q -> fp16 hi/lo (scale folded) ----
        size_t i = (size_t)(bid - 1536) * 256 + t;
        float4 a = ((const float4*)Q)[i * 2];
        float4 b = ((const float4*)Q)[i * 2 + 1];
        const float s = 0.125f;
        uint32_t h[4], l[4];
        split2h(a.x * s, a.y * s, h[0], l[0]);
        split2h(a.z * s, a.w * s, h[1], l[1]);
        split2h(b.x * s, b.y * s, h[2], l[2]);
        split2h(b.z * s, b.w * s, h[3], l[3]);
        ((uint4*)g_Qh)[i] = make_uint4(h[0], h[1], h[2], h[3]);
        ((uint4*)g_Ql)[i] = make_uint4(l[0], l[1], l[2], l[3]);
    }
}

// ---------------------------------------------------------------------------
// 2-pass MMA phase for k1: D = Qh*K + Ql*K (K single fp16).
// Buffer: Qh@+0 (16K), Ql@+16384 (16K), K@+32768 (8K) => 40KB per buffer
// ---------------------------------------------------------------------------
__device__ __forceinline__ void mma_phase(uint32_t buf, float Dc[2][4][4],
                                          int arow, int brow, int acol) {
#pragma unroll
    for (int ks = 0; ks < 4; ks++) {
        uint32_t aH[2][4], aL[2][4], bF[2][4];
#pragma unroll
        for (int mt = 0; mt < 2; mt++)
            ldmx4(aH[mt], buf + SW128((uint32_t)((arow + mt * 16) * 128 + ks * 32 + acol)));
#pragma unroll
        for (int np = 0; np < 2; np++)
            ldmx4(bF[np], buf + 32768 + SW128((uint32_t)((brow + np * 16) * 128 + ks * 32 + acol)));
#pragma unroll
        for (int mt = 0; mt < 2; mt++)
#pragma unroll
            for (int np = 0; np < 2; np++) {
                mma16816(Dc[mt][np * 2],     aH[mt], bF[np][0], bF[np][2]);
                mma16816(Dc[mt][np * 2 + 1], aH[mt], bF[np][1], bF[np][3]);
            }
#pragma unroll
        for (int mt = 0; mt < 2; mt++)
            ldmx4(aL[mt], buf + 16384 + SW128((uint32_t)((arow + mt * 16) * 128 + ks * 32 + acol)));
#pragma unroll
        for (int mt = 0; mt < 2; mt++)
#pragma unroll
            for (int np = 0; np < 2; np++) {
                mma16816(Dc[mt][np * 2],     aL[mt], bF[np][0], bF[np][2]);
                mma16816(Dc[mt][np * 2 + 1], aL[mt], bF[np][1], bF[np][3]);
            }
    }
}

// ===========================================================================
// k1: scores. Double-buffered cp.async staging of Q(hi/lo)+K(single);
// P/rdenom stored fragment-tiled (coalesced STG.128).
// ===========================================================================
__device__ __forceinline__ void k1_stage(uint32_t buf, int tid, size_t qbase, size_t kbase) {
#pragma unroll
    for (int it = 0; it < 4; it++) {
        int u = tid + it * 256;
        int q = u >> 3, g = u & 7;
        uint32_t dst = buf + SW128((uint32_t)(q * 128 + g * 16));
        cp16(dst,         g_Qh + qbase + q * D_ + g * 8);
        cp16(dst + 16384, g_Ql + qbase + q * D_ + g * 8);
    }
#pragma unroll
    for (int it = 0; it < 2; it++) {
        int u = tid + it * 256;
        int k = u >> 3, g = u & 7;
        cp16(buf + 32768 + SW128((uint32_t)(k * 128 + g * 16)),
             g_Kf + kbase + k * D_ + g * 8);
    }
    cp_commit();
}

__global__ __launch_bounds__(256, 2) void k1_scores() {
    extern __shared__ __align__(128) uint8_t smem[];   // 81920
    const uint32_t sb = smem_u32(smem);
    const int tid = threadIdx.x;
    const int lane = tid & 31, w = tid >> 5;
    const int kt = blockIdx.x, qt = blockIdx.y;
    const int q0 = qt * 128, k0 = kt * 64;
    const int wq = w >> 1, wk = w & 1;
    const int arow = wq * 32 + (lane & 15);
    const int brow = wk * 32 + (lane & 15);
    const int acol = (lane >> 4) * 16;
    const int fragoff = w * 1024 + lane * 4;

    float denom[2][4][4];
#pragma unroll
    for (int mt = 0; mt < 2; mt++)
#pragma unroll
        for (int nt = 0; nt < 4; nt++)
#pragma unroll
            for (int r = 0; r < 4; r++) denom[mt][nt][r] = 0.0f;

    k1_stage(sb,         tid, (size_t)0 * ND + (size_t)q0 * D_, (size_t)0 * ND + (size_t)k0 * D_);
    k1_stage(sb + 40960, tid, (size_t)1 * ND + (size_t)q0 * D_, (size_t)1 * ND + (size_t)k0 * D_);

    for (int b = 0; b < B_; b++) {
        const uint32_t buf = sb + (b & 1) * 40960;
        if (b < B_ - 1) asm volatile("cp.async.wait_group 1;" ::: "memory");
        else            asm volatile("cp.async.wait_group 0;" ::: "memory");
        __syncthreads();

        float Dc[2][4][4];
#pragma unroll
        for (int mt = 0; mt < 2; mt++)
#pragma unroll
            for (int nt = 0; nt < 4; nt++)
#pragma unroll
                for (int r = 0; r < 4; r++) Dc[mt][nt][r] = 0.0f;

        mma_phase(buf, Dc, arow, brow, acol);

        // ---- exp + denom + fragment-tiled coalesced P store ----
        float* Pb = g_P + (((size_t)b * 16 + qt) * 32 + kt) * TILE + fragoff;
#pragma unroll
        for (int mt = 0; mt < 2; mt++)
#pragma unroll
            for (int nt = 0; nt < 4; nt++) {
                float e0 = __expf(Dc[mt][nt][0]);
                float e1 = __expf(Dc[mt][nt][1]);
                float e2 = __expf(Dc[mt][nt][2]);
                float e3 = __expf(Dc[mt][nt][3]);
                denom[mt][nt][0] += e0; denom[mt][nt][1] += e1;
                denom[mt][nt][2] += e2; denom[mt][nt][3] += e3;
                *(float4*)(Pb + (mt * 4 + nt) * 128) = make_float4(e0, e1, e2, e3);
            }
        __syncthreads();
        if (b + 2 < B_)
            k1_stage(buf, tid, (size_t)(b + 2) * ND + (size_t)q0 * D_,
                               (size_t)(b + 2) * ND + (size_t)k0 * D_);
    }

    // ---- rdenom (fragment-tiled, coalesced) ----
    float* Rb = g_rdenom + ((size_t)qt * 32 + kt) * TILE + fragoff;
#pragma unroll
    for (int mt = 0; mt < 2; mt++)
#pragma unroll
        for (int nt = 0; nt < 4; nt++)
            *(float4*)(Rb + (mt * 4 + nt) * 128) = make_float4(
                1.0f / denom[mt][nt][0], 1.0f / denom[mt][nt][1],
                1.0f / denom[mt][nt][2], 1.0f / denom[mt][nt][3]);
}

// ===========================================================================
// k2: out[b] = (P[b]*rdenom) @ V[b]. Block (b, qt), 256 thr.
// A = normalized P split fp16 hi/lo (from fp32, exact-ish); V single fp16.
// ALL operands via coalesced LDG; no smem/sync in main loop.
// ===========================================================================
__global__ __launch_bounds__(256, 2) void k2_out(float* __restrict__ O) {
    __shared__ __align__(16) float red[8192];   // 32KB, epilogue only
    const int tid = threadIdx.x;
    const int lane = tid & 31, w = tid >> 5;
    const int b = blockIdx.x, qt = blockIdx.y;
    const int wq2 = w >> 1, kh = w & 1;
    const int fragoff = w * 1024 + lane * 4;

    float Dc[2][8][4];
#pragma unroll
    for (int mt = 0; mt < 2; mt++)
#pragma unroll
        for (int j = 0; j < 8; j++)
#pragma unroll
            for (int r = 0; r < 4; r++) Dc[mt][j][r] = 0.0f;

    for (int c = 0; c < 32; c++) {
        const float* pA = g_P + (((size_t)b * 16 + qt) * 32 + c) * TILE + fragoff;
        const float* pR = g_rdenom + ((size_t)qt * 32 + c) * TILE + fragoff;
        const size_t vbase = ((size_t)(b * 32 + c) * 16 + kh * 8) * 32 + lane;

#pragma unroll
        for (int kg = 0; kg < 2; kg++) {
            uint32_t aH[2][4], aL[2][4];
#pragma unroll
            for (int mt = 0; mt < 2; mt++)
#pragma unroll
                for (int hf = 0; hf < 2; hf++) {
                    int i = mt * 4 + kg * 2 + hf;
                    float4 p = *(const float4*)(pA + i * 128);
                    float4 r = *(const float4*)(pR + i * 128);
                    uint32_t h01, l01, h23, l23;
                    split2h(p.x * r.x, p.y * r.y, h01, l01);
                    split2h(p.z * r.z, p.w * r.w, h23, l23);
                    aH[mt][hf * 2] = h01; aH[mt][hf * 2 + 1] = h23;
                    aL[mt][hf * 2] = l01; aL[mt][hf * 2 + 1] = l23;
                }
#pragma unroll
            for (int g16 = 0; g16 < 4; g16++) {
                uint4 vh = g_VFf[vbase + (size_t)(kg * 4 + g16) * 32];
#pragma unroll
                for (int mt = 0; mt < 2; mt++) {
                    mma16816(Dc[mt][g16 * 2],     aH[mt], vh.x, vh.z);
                    mma16816(Dc[mt][g16 * 2 + 1], aH[mt], vh.y, vh.w);
                    mma16816(Dc[mt][g16 * 2],     aL[mt], vh.x, vh.z);
                    mma16816(Dc[mt][g16 * 2 + 1], aL[mt], vh.y, vh.w);
                }
            }
        }
    }

    // ---- cross-warp (kh) reduction via smem, then O store ----
    if (kh == 1) {
#pragma unroll
        for (int mt = 0; mt < 2; mt++)
#pragma unroll
            for (int j = 0; j < 8; j++)
                *(float4*)(red + wq2 * 2048 + (mt * 8 + j) * 128 + lane * 4) =
                    make_float4(Dc[mt][j][0], Dc[mt][j][1], Dc[mt][j][2], Dc[mt][j][3]);
    }
    __syncthreads();
    if (kh == 0) {
#pragma unroll
        for (int mt = 0; mt < 2; mt++) {
            int r0 = qt * 128 + wq2 * 32 + mt * 16 + (lane >> 2);
#pragma unroll
            for (int j = 0; j < 8; j++) {
                float4 o = *(float4*)(red + wq2 * 2048 + (mt * 8 + j) * 128 + lane * 4);
                float v0 = Dc[mt][j][0] + o.x;
                float v1 = Dc[mt][j][1] + o.y;
                float v2 = Dc[mt][j][2] + o.z;
                float v3 = Dc[mt][j][3] + o.w;
                int cc = j * 8 + 2 * (lane & 3);
                *(float2*)(O + ((size_t)b * N_ + r0) * D_ + cc)     = make_float2(v0, v1);
                *(float2*)(O + ((size_t)b * N_ + r0 + 8) * D_ + cc) = make_float2(v2, v3);
            }
        }
    }
}

// ===========================================================================
extern "C" void kernel_launch(void* const* d_in, const int* in_sizes, int n_in,
                              void* d_out, int out_size) {
    const float* Q = (const float*)d_in[0];
    const float* K = (const float*)d_in[1];
    const float* V = (const float*)d_in[2];
    float* O = (float*)d_out;

    cudaFuncSetAttribute(k1_scores, cudaFuncAttributeMaxDynamicSharedMemorySize, 81920);

    k0_prep<<<2560, 256>>>(Q, K, V);
    k1_scores<<<dim3(N_ / 64, N_ / 128), 256, 81920>>>();   // (kt, qt)
    k2_out<<<dim3(B_, N_ / 128), 256>>>(O);                 // (b, qt)
}

// round 13
// speedup vs baseline: 1.8382x; 1.3235x over previous
#include <cuda_runtime.h>
#include <cuda_fp16.h>
#include <cstdint>
#include <cstddef>

constexpr int B_ = 16, N_ = 2048, D_ = 64;
constexpr size_t ND = (size_t)N_ * D_;
constexpr size_t N2 = (size_t)N_ * N_;
// fragment-tiled P: tile (qt,kt) = 128q x 64k = 8192 elements
// idx = w*1024 + (mt*4+nt)*128 + lane*4 + e
constexpr int TILE = 8192;

// ---- scratch (__device__ globals; no allocations allowed) ----
__device__ __half g_P[(size_t)B_ * N2];       // fragment-tiled exp(scores), fp16 (134MB)
__device__ float g_rdenom[N2];                // fragment-tiled, fp32 (16MB)
__device__ __half g_Qh[(size_t)B_ * ND];      // fp16 hi (scale folded)
__device__ __half g_Ql[(size_t)B_ * ND];      // fp16 lo residual
__device__ __half g_Kf[(size_t)B_ * ND];      // fp16 single plane
// V in B-fragment layout (fp16 single plane):
// slot = ((b*32 + c)*16 + kh*8 + kg*4 + g16), entry [slot*32 + lane]
__device__ uint4 g_VFf[262144];               // 4MB

#define SW128(o) ((o) ^ (((o) >> 3) & 0x70))

__device__ __forceinline__ uint32_t smem_u32(const void* p) {
    uint32_t a;
    asm("{ .reg .u64 t; cvta.to.shared.u64 t, %1; cvt.u32.u64 %0, t; }" : "=r"(a) : "l"(p));
    return a;
}
__device__ __forceinline__ void ldmx4(uint32_t* r, uint32_t addr) {
    asm volatile("ldmatrix.sync.aligned.m8n8.x4.shared.b16 {%0,%1,%2,%3}, [%4];"
                 : "=r"(r[0]), "=r"(r[1]), "=r"(r[2]), "=r"(r[3]) : "r"(addr));
}
__device__ __forceinline__ void mma16816(float* d, const uint32_t* a, uint32_t b0, uint32_t b1) {
    asm volatile(
        "mma.sync.aligned.m16n8k16.row.col.f32.f16.f16.f32 "
        "{%0,%1,%2,%3}, {%4,%5,%6,%7}, {%8,%9}, {%0,%1,%2,%3};"
        : "+f"(d[0]), "+f"(d[1]), "+f"(d[2]), "+f"(d[3])
        : "r"(a[0]), "r"(a[1]), "r"(a[2]), "r"(a[3]), "r"(b0), "r"(b1));
}
__device__ __forceinline__ uint32_t pack2h(float a, float b) {
    __half2 v = __floats2half2_rn(a, b);
    return *(uint32_t*)&v;
}
// split into fp16 hi + fp16 lo residual
__device__ __forceinline__ void split2h(float a, float b, uint32_t& h, uint32_t& l) {
    __half ha = __float2half_rn(a), hb = __float2half_rn(b);
    float la = a - __half2float(ha), lb = b - __half2float(hb);
    __half2 hv; hv.x = ha; hv.y = hb;
    __half2 lv; lv.x = __float2half_rn(la); lv.y = __float2half_rn(lb);
    h = *(uint32_t*)&hv;
    l = *(uint32_t*)&lv;
}
__device__ __forceinline__ void cp16(uint32_t dst, const void* src) {
    asm volatile("cp.async.cg.shared.global [%0], [%1], 16;" :: "r"(dst), "l"(src));
}
__device__ __forceinline__ void cp_commit() {
    asm volatile("cp.async.commit_group;" ::: "memory");
}

// ===========================================================================
// k0_prep (merged): flat grid of 2560 blocks x 256 thr
//   [0,1024):    K -> single fp16 plane
//   [1024,1536): V -> B-fragment layout (fp16 single plane) via smem tile
//   [1536,2560): Q -> fp16 hi/lo planes (scale folded)
// ===========================================================================
__global__ __launch_bounds__(256) void k0_prep(const float* __restrict__ Q,
                                               const float* __restrict__ K,
                                               const float* __restrict__ V) {
    __shared__ float smv[64][65];
    const int bid = blockIdx.x;
    const int t = threadIdx.x;

    if (bid < 1024) {
        // ---- K -> fp16 (single plane) ----
        size_t i = (size_t)bid * 256 + t;   // unit of 8 floats
        float4 a = ((const float4*)K)[i * 2];
        float4 b = ((const float4*)K)[i * 2 + 1];
        uint4 o;
        o.x = pack2h(a.x, a.y);
        o.y = pack2h(a.z, a.w);
        o.z = pack2h(b.x, b.y);
        o.w = pack2h(b.z, b.w);
        ((uint4*)g_Kf)[i] = o;
    } else if (bid < 1536) {
        // ---- V -> B-fragment layout (fp16) ----
        const int v = bid - 1024;
        const int b = v >> 5, c = v & 31;
        const int k0 = c * 64;
        const float* Vb = V + ((size_t)b * N_ + k0) * D_;
#pragma unroll
        for (int it = 0; it < 4; it++) {
            int f = t + it * 256;
            int k = f >> 4, d4 = f & 15;
            float4 vv = *(const float4*)(Vb + k * D_ + d4 * 4);
            smv[k][d4 * 4 + 0] = vv.x;
            smv[k][d4 * 4 + 1] = vv.y;
            smv[k][d4 * 4 + 2] = vv.z;
            smv[k][d4 * 4 + 3] = vv.w;
        }
        __syncthreads();
        const int lane = t & 31;
        const int wslot = t >> 5;   // 0..7, 2 slots each
#pragma unroll
        for (int r = 0; r < 2; r++) {
            int s = wslot * 2 + r;                      // 0..15
            int kh = s >> 3, kg = (s >> 2) & 1, g16 = s & 3;
            int d0 = g16 * 16, kl0 = kh * 32 + kg * 16;
            uint32_t h[4];
#pragma unroll
            for (int i = 0; i < 4; i++) {
                int d = d0 + (i & 1) * 8 + (lane >> 2);
                int kk = kl0 + (i >> 1) * 8 + (lane & 3) * 2;
                h[i] = pack2h(smv[kk][d], smv[kk + 1][d]);
            }
            size_t slot = ((size_t)(b * 32 + c) * 16 + s) * 32 + lane;
            g_VFf[slot] = make_uint4(h[0], h[1], h[2], h[3]);
        }
    } else {
        // ---- Q -> fp16 hi/lo (scale folded) ----
        size_t i = (size_t)(bid - 1536) * 256 + t;
        float4 a = ((const float4*)Q)[i * 2];
        float4 b = ((const float4*)Q)[i * 2 + 1];
        const float s = 0.125f;
        uint32_t h[4], l[4];
        split2h(a.x * s, a.y * s, h[0], l[0]);
        split2h(a.z * s, a.w * s, h[1], l[1]);
        split2h(b.x * s, b.y * s, h[2], l[2]);
        split2h(b.z * s, b.w * s, h[3], l[3]);
        ((uint4*)g_Qh)[i] = make_uint4(h[0], h[1], h[2], h[3]);
        ((uint4*)g_Ql)[i] = make_uint4(l[0], l[1], l[2], l[3]);
    }
}

// ---------------------------------------------------------------------------
// 2-pass MMA phase for k1: D = Qh*K + Ql*K (K single fp16).
// Buffer: Qh@+0 (16K), Ql@+16384 (16K), K@+32768 (8K) => 40KB per buffer
// ---------------------------------------------------------------------------
__device__ __forceinline__ void mma_phase(uint32_t buf, float Dc[2][4][4],
                                          int arow, int brow, int acol) {
#pragma unroll
    for (int ks = 0; ks < 4; ks++) {
        uint32_t aH[2][4], aL[2][4], bF[2][4];
#pragma unroll
        for (int mt = 0; mt < 2; mt++)
            ldmx4(aH[mt], buf + SW128((uint32_t)((arow + mt * 16) * 128 + ks * 32 + acol)));
#pragma unroll
        for (int np = 0; np < 2; np++)
            ldmx4(bF[np], buf + 32768 + SW128((uint32_t)((brow + np * 16) * 128 + ks * 32 + acol)));
#pragma unroll
        for (int mt = 0; mt < 2; mt++)
#pragma unroll
            for (int np = 0; np < 2; np++) {
                mma16816(Dc[mt][np * 2],     aH[mt], bF[np][0], bF[np][2]);
                mma16816(Dc[mt][np * 2 + 1], aH[mt], bF[np][1], bF[np][3]);
            }
#pragma unroll
        for (int mt = 0; mt < 2; mt++)
            ldmx4(aL[mt], buf + 16384 + SW128((uint32_t)((arow + mt * 16) * 128 + ks * 32 + acol)));
#pragma unroll
        for (int mt = 0; mt < 2; mt++)
#pragma unroll
            for (int np = 0; np < 2; np++) {
                mma16816(Dc[mt][np * 2],     aL[mt], bF[np][0], bF[np][2]);
                mma16816(Dc[mt][np * 2 + 1], aL[mt], bF[np][1], bF[np][3]);
            }
    }
}

// ===========================================================================
// k1: scores. Double-buffered cp.async staging of Q(hi/lo)+K(single);
// P stored fp16 fragment-tiled (coalesced STG.64), rdenom fp32.
// ===========================================================================
__device__ __forceinline__ void k1_stage(uint32_t buf, int tid, size_t qbase, size_t kbase) {
#pragma unroll
    for (int it = 0; it < 4; it++) {
        int u = tid + it * 256;
        int q = u >> 3, g = u & 7;
        uint32_t dst = buf + SW128((uint32_t)(q * 128 + g * 16));
        cp16(dst,         g_Qh + qbase + q * D_ + g * 8);
        cp16(dst + 16384, g_Ql + qbase + q * D_ + g * 8);
    }
#pragma unroll
    for (int it = 0; it < 2; it++) {
        int u = tid + it * 256;
        int k = u >> 3, g = u & 7;
        cp16(buf + 32768 + SW128((uint32_t)(k * 128 + g * 16)),
             g_Kf + kbase + k * D_ + g * 8);
    }
    cp_commit();
}

__global__ __launch_bounds__(256, 2) void k1_scores() {
    extern __shared__ __align__(128) uint8_t smem[];   // 81920
    const uint32_t sb = smem_u32(smem);
    const int tid = threadIdx.x;
    const int lane = tid & 31, w = tid >> 5;
    const int kt = blockIdx.x, qt = blockIdx.y;
    const int q0 = qt * 128, k0 = kt * 64;
    const int wq = w >> 1, wk = w & 1;
    const int arow = wq * 32 + (lane & 15);
    const int brow = wk * 32 + (lane & 15);
    const int acol = (lane >> 4) * 16;
    const int fragoff = w * 1024 + lane * 4;

    float denom[2][4][4];
#pragma unroll
    for (int mt = 0; mt < 2; mt++)
#pragma unroll
        for (int nt = 0; nt < 4; nt++)
#pragma unroll
            for (int r = 0; r < 4; r++) denom[mt][nt][r] = 0.0f;

    k1_stage(sb,         tid, (size_t)0 * ND + (size_t)q0 * D_, (size_t)0 * ND + (size_t)k0 * D_);
    k1_stage(sb + 40960, tid, (size_t)1 * ND + (size_t)q0 * D_, (size_t)1 * ND + (size_t)k0 * D_);

    for (int b = 0; b < B_; b++) {
        const uint32_t buf = sb + (b & 1) * 40960;
        if (b < B_ - 1) asm volatile("cp.async.wait_group 1;" ::: "memory");
        else            asm volatile("cp.async.wait_group 0;" ::: "memory");
        __syncthreads();

        float Dc[2][4][4];
#pragma unroll
        for (int mt = 0; mt < 2; mt++)
#pragma unroll
            for (int nt = 0; nt < 4; nt++)
#pragma unroll
                for (int r = 0; r < 4; r++) Dc[mt][nt][r] = 0.0f;

        mma_phase(buf, Dc, arow, brow, acol);

        // ---- exp + denom + fragment-tiled coalesced fp16 P store ----
        __half* Pb = g_P + (((size_t)b * 16 + qt) * 32 + kt) * TILE + fragoff;
#pragma unroll
        for (int mt = 0; mt < 2; mt++)
#pragma unroll
            for (int nt = 0; nt < 4; nt++) {
                float e0 = __expf(Dc[mt][nt][0]);
                float e1 = __expf(Dc[mt][nt][1]);
                float e2 = __expf(Dc[mt][nt][2]);
                float e3 = __expf(Dc[mt][nt][3]);
                denom[mt][nt][0] += e0; denom[mt][nt][1] += e1;
                denom[mt][nt][2] += e2; denom[mt][nt][3] += e3;
                *(uint2*)(Pb + (mt * 4 + nt) * 128) =
                    make_uint2(pack2h(e0, e1), pack2h(e2, e3));
            }
        __syncthreads();
        if (b + 2 < B_)
            k1_stage(buf, tid, (size_t)(b + 2) * ND + (size_t)q0 * D_,
                               (size_t)(b + 2) * ND + (size_t)k0 * D_);
    }

    // ---- rdenom (fragment-tiled, coalesced, fp32) ----
    float* Rb = g_rdenom + ((size_t)qt * 32 + kt) * TILE + fragoff;
#pragma unroll
    for (int mt = 0; mt < 2; mt++)
#pragma unroll
        for (int nt = 0; nt < 4; nt++)
            *(float4*)(Rb + (mt * 4 + nt) * 128) = make_float4(
                1.0f / denom[mt][nt][0], 1.0f / denom[mt][nt][1],
                1.0f / denom[mt][nt][2], 1.0f / denom[mt][nt][3]);
}

// ===========================================================================
// k2: out[b] = (P[b]*rdenom) @ V[b]. Block (b, qt), 256 thr.
// A = fp16(P)*rdenom, single plane; V single fp16. Half the MMAs of R12.
// ALL operands via coalesced LDG; no smem/sync in main loop.
// ===========================================================================
__global__ __launch_bounds__(256, 2) void k2_out(float* __restrict__ O) {
    __shared__ __align__(16) float red[8192];   // 32KB, epilogue only
    const int tid = threadIdx.x;
    const int lane = tid & 31, w = tid >> 5;
    const int b = blockIdx.x, qt = blockIdx.y;
    const int wq2 = w >> 1, kh = w & 1;
    const int fragoff = w * 1024 + lane * 4;

    float Dc[2][8][4];
#pragma unroll
    for (int mt = 0; mt < 2; mt++)
#pragma unroll
        for (int j = 0; j < 8; j++)
#pragma unroll
            for (int r = 0; r < 4; r++) Dc[mt][j][r] = 0.0f;

    for (int c = 0; c < 32; c++) {
        const __half* pA = g_P + (((size_t)b * 16 + qt) * 32 + c) * TILE + fragoff;
        const float* pR = g_rdenom + ((size_t)qt * 32 + c) * TILE + fragoff;
        const size_t vbase = ((size_t)(b * 32 + c) * 16 + kh * 8) * 32 + lane;

#pragma unroll
        for (int kg = 0; kg < 2; kg++) {
            uint32_t aH[2][4];
#pragma unroll
            for (int mt = 0; mt < 2; mt++)
#pragma unroll
                for (int hf = 0; hf < 2; hf++) {
                    int i = mt * 4 + kg * 2 + hf;
                    uint2 pv = *(const uint2*)(pA + i * 128);
                    float4 r = *(const float4*)(pR + i * 128);
                    float2 p01 = __half22float2(*(__half2*)&pv.x);
                    float2 p23 = __half22float2(*(__half2*)&pv.y);
                    aH[mt][hf * 2]     = pack2h(p01.x * r.x, p01.y * r.y);
                    aH[mt][hf * 2 + 1] = pack2h(p23.x * r.z, p23.y * r.w);
                }
#pragma unroll
            for (int g16 = 0; g16 < 4; g16++) {
                uint4 vh = g_VFf[vbase + (size_t)(kg * 4 + g16) * 32];
#pragma unroll
                for (int mt = 0; mt < 2; mt++) {
                    mma16816(Dc[mt][g16 * 2],     aH[mt], vh.x, vh.z);
                    mma16816(Dc[mt][g16 * 2 + 1], aH[mt], vh.y, vh.w);
                }
            }
        }
    }

    // ---- cross-warp (kh) reduction via smem, then O store ----
    if (kh == 1) {
#pragma unroll
        for (int mt = 0; mt < 2; mt++)
#pragma unroll
            for (int j = 0; j < 8; j++)
                *(float4*)(red + wq2 * 2048 + (mt * 8 + j) * 128 + lane * 4) =
                    make_float4(Dc[mt][j][0], Dc[mt][j][1], Dc[mt][j][2], Dc[mt][j][3]);
    }
    __syncthreads();
    if (kh == 0) {
#pragma unroll
        for (int mt = 0; mt < 2; mt++) {
            int r0 = qt * 128 + wq2 * 32 + mt * 16 + (lane >> 2);
#pragma unroll
            for (int j = 0; j < 8; j++) {
                float4 o = *(float4*)(red + wq2 * 2048 + (mt * 8 + j) * 128 + lane * 4);
                float v0 = Dc[mt][j][0] + o.x;
                float v1 = Dc[mt][j][1] + o.y;
                float v2 = Dc[mt][j][2] + o.z;
                float v3 = Dc[mt][j][3] + o.w;
                int cc = j * 8 + 2 * (lane & 3);
                *(float2*)(O + ((size_t)b * N_ + r0) * D_ + cc)     = make_float2(v0, v1);
                *(float2*)(O + ((size_t)b * N_ + r0 + 8) * D_ + cc) = make_float2(v2, v3);
            }
        }
    }
}

// ===========================================================================
extern "C" void kernel_launch(void* const* d_in, const int* in_sizes, int n_in,
                              void* d_out, int out_size) {
    const float* Q = (const float*)d_in[0];
    const float* K = (const float*)d_in[1];
    const float* V = (const float*)d_in[2];
    float* O = (float*)d_out;

    cudaFuncSetAttribute(k1_scores, cudaFuncAttributeMaxDynamicSharedMemorySize, 81920);

    k0_prep<<<2560, 256>>>(Q, K, V);
    k1_scores<<<dim3(N_ / 64, N_ / 128), 256, 81920>>>();   // (kt, qt)
    k2_out<<<dim3(B_, N_ / 128), 256>>>(O);                 // (b, qt)
}

// round 14
// speedup vs baseline: 2.1924x; 1.1927x over previous
#include <cuda_runtime.h>
#include <cuda_fp16.h>
#include <cstdint>
#include <cstddef>

constexpr int B_ = 16, N_ = 2048, D_ = 64;
constexpr size_t ND = (size_t)N_ * D_;
constexpr size_t N2 = (size_t)N_ * N_;
// fragment-tiled P: tile (qt,kt) = 128q x 64k = 8192 elements
// idx = w*1024 + (mt*4+nt)*128 + lane*4 + e
constexpr int TILE = 8192;

// ---- scratch (__device__ globals; no allocations allowed) ----
__device__ __half g_P[(size_t)B_ * N2];       // fragment-tiled exp(scores), fp16 (134MB)
__device__ float g_rdenom[N2];                // fragment-tiled, fp32 (16MB)
__device__ __half g_Qf[(size_t)B_ * ND];      // fp16 single plane (scale folded)
__device__ __half g_Kf[(size_t)B_ * ND];      // fp16 single plane
// V in B-fragment layout (fp16 single plane):
// slot = ((b*32 + c)*16 + kh*8 + kg*4 + g16), entry [slot*32 + lane]
__device__ uint4 g_VFf[262144];               // 4MB

#define SW128(o) ((o) ^ (((o) >> 3) & 0x70))

__device__ __forceinline__ uint32_t smem_u32(const void* p) {
    uint32_t a;
    asm("{ .reg .u64 t; cvta.to.shared.u64 t, %1; cvt.u32.u64 %0, t; }" : "=r"(a) : "l"(p));
    return a;
}
__device__ __forceinline__ void ldmx4(uint32_t* r, uint32_t addr) {
    asm volatile("ldmatrix.sync.aligned.m8n8.x4.shared.b16 {%0,%1,%2,%3}, [%4];"
                 : "=r"(r[0]), "=r"(r[1]), "=r"(r[2]), "=r"(r[3]) : "r"(addr));
}
__device__ __forceinline__ void mma16816(float* d, const uint32_t* a, uint32_t b0, uint32_t b1) {
    asm volatile(
        "mma.sync.aligned.m16n8k16.row.col.f32.f16.f16.f32 "
        "{%0,%1,%2,%3}, {%4,%5,%6,%7}, {%8,%9}, {%0,%1,%2,%3};"
        : "+f"(d[0]), "+f"(d[1]), "+f"(d[2]), "+f"(d[3])
        : "r"(a[0]), "r"(a[1]), "r"(a[2]), "r"(a[3]), "r"(b0), "r"(b1));
}
__device__ __forceinline__ uint32_t pack2h(float a, float b) {
    __half2 v = __floats2half2_rn(a, b);
    return *(uint32_t*)&v;
}
__device__ __forceinline__ void cp16(uint32_t dst, const void* src) {
    asm volatile("cp.async.cg.shared.global [%0], [%1], 16;" :: "r"(dst), "l"(src));
}
__device__ __forceinline__ void cp_commit() {
    asm volatile("cp.async.commit_group;" ::: "memory");
}

// ===========================================================================
// k0_prep (merged): flat grid of 2560 blocks x 256 thr
//   [0,1024):    K -> single fp16 plane
//   [1024,1536): V -> B-fragment layout (fp16 single plane) via smem tile
//   [1536,2560): Q -> single fp16 plane (scale folded)
// ===========================================================================
__global__ __launch_bounds__(256) void k0_prep(const float* __restrict__ Q,
                                               const float* __restrict__ K,
                                               const float* __restrict__ V) {
    __shared__ float smv[64][65];
    const int bid = blockIdx.x;
    const int t = threadIdx.x;

    if (bid < 1024) {
        // ---- K -> fp16 (single plane) ----
        size_t i = (size_t)bid * 256 + t;   // unit of 8 floats
        float4 a = ((const float4*)K)[i * 2];
        float4 b = ((const float4*)K)[i * 2 + 1];
        uint4 o;
        o.x = pack2h(a.x, a.y);
        o.y = pack2h(a.z, a.w);
        o.z = pack2h(b.x, b.y);
        o.w = pack2h(b.z, b.w);
        ((uint4*)g_Kf)[i] = o;
    } else if (bid < 1536) {
        // ---- V -> B-fragment layout (fp16) ----
        const int v = bid - 1024;
        const int b = v >> 5, c = v & 31;
        const int k0 = c * 64;
        const float* Vb = V + ((size_t)b * N_ + k0) * D_;
#pragma unroll
        for (int it = 0; it < 4; it++) {
            int f = t + it * 256;
            int k = f >> 4, d4 = f & 15;
            float4 vv = *(const float4*)(Vb + k * D_ + d4 * 4);
            smv[k][d4 * 4 + 0] = vv.x;
            smv[k][d4 * 4 + 1] = vv.y;
            smv[k][d4 * 4 + 2] = vv.z;
            smv[k][d4 * 4 + 3] = vv.w;
        }
        __syncthreads();
        const int lane = t & 31;
        const int wslot = t >> 5;   // 0..7, 2 slots each
#pragma unroll
        for (int r = 0; r < 2; r++) {
            int s = wslot * 2 + r;                      // 0..15
            int kh = s >> 3, kg = (s >> 2) & 1, g16 = s & 3;
            int d0 = g16 * 16, kl0 = kh * 32 + kg * 16;
            uint32_t h[4];
#pragma unroll
            for (int i = 0; i < 4; i++) {
                int d = d0 + (i & 1) * 8 + (lane >> 2);
                int kk = kl0 + (i >> 1) * 8 + (lane & 3) * 2;
                h[i] = pack2h(smv[kk][d], smv[kk + 1][d]);
            }
            size_t slot = ((size_t)(b * 32 + c) * 16 + s) * 32 + lane;
            g_VFf[slot] = make_uint4(h[0], h[1], h[2], h[3]);
        }
    } else {
        // ---- Q -> fp16 single plane (scale folded) ----
        size_t i = (size_t)(bid - 1536) * 256 + t;
        float4 a = ((const float4*)Q)[i * 2];
        float4 b = ((const float4*)Q)[i * 2 + 1];
        const float s = 0.125f;
        uint4 o;
        o.x = pack2h(a.x * s, a.y * s);
        o.y = pack2h(a.z * s, a.w * s);
        o.z = pack2h(b.x * s, b.y * s);
        o.w = pack2h(b.z * s, b.w * s);
        ((uint4*)g_Qf)[i] = o;
    }
}

// ---------------------------------------------------------------------------
// Single-pass MMA phase for k1: D = Qf * Kf (both single fp16).
// Buffer: Q@+0 (16K), K@+16384 (8K) => 24KB per buffer
// ---------------------------------------------------------------------------
__device__ __forceinline__ void mma_phase(uint32_t buf, float Dc[2][4][4],
                                          int arow, int brow, int acol) {
#pragma unroll
    for (int ks = 0; ks < 4; ks++) {
        uint32_t aF[2][4], bF[2][4];
#pragma unroll
        for (int mt = 0; mt < 2; mt++)
            ldmx4(aF[mt], buf + SW128((uint32_t)((arow + mt * 16) * 128 + ks * 32 + acol)));
#pragma unroll
        for (int np = 0; np < 2; np++)
            ldmx4(bF[np], buf + 16384 + SW128((uint32_t)((brow + np * 16) * 128 + ks * 32 + acol)));
#pragma unroll
        for (int mt = 0; mt < 2; mt++)
#pragma unroll
            for (int np = 0; np < 2; np++) {
                mma16816(Dc[mt][np * 2],     aF[mt], bF[np][0], bF[np][2]);
                mma16816(Dc[mt][np * 2 + 1], aF[mt], bF[np][1], bF[np][3]);
            }
    }
}

// ===========================================================================
// k1: scores. Double-buffered cp.async staging of Q+K (single fp16 planes);
// P stored fp16 fragment-tiled (coalesced STG.64), rdenom fp32.
// ===========================================================================
__device__ __forceinline__ void k1_stage(uint32_t buf, int tid, size_t qbase, size_t kbase) {
#pragma unroll
    for (int it = 0; it < 4; it++) {
        int u = tid + it * 256;
        int q = u >> 3, g = u & 7;
        cp16(buf + SW128((uint32_t)(q * 128 + g * 16)),
             g_Qf + qbase + q * D_ + g * 8);
    }
#pragma unroll
    for (int it = 0; it < 2; it++) {
        int u = tid + it * 256;
        int k = u >> 3, g = u & 7;
        cp16(buf + 16384 + SW128((uint32_t)(k * 128 + g * 16)),
             g_Kf + kbase + k * D_ + g * 8);
    }
    cp_commit();
}

__global__ __launch_bounds__(256, 2) void k1_scores() {
    extern __shared__ __align__(128) uint8_t smem[];   // 49152
    const uint32_t sb = smem_u32(smem);
    const int tid = threadIdx.x;
    const int lane = tid & 31, w = tid >> 5;
    const int kt = blockIdx.x, qt = blockIdx.y;
    const int q0 = qt * 128, k0 = kt * 64;
    const int wq = w >> 1, wk = w & 1;
    const int arow = wq * 32 + (lane & 15);
    const int brow = wk * 32 + (lane & 15);
    const int acol = (lane >> 4) * 16;
    const int fragoff = w * 1024 + lane * 4;

    float denom[2][4][4];
#pragma unroll
    for (int mt = 0; mt < 2; mt++)
#pragma unroll
        for (int nt = 0; nt < 4; nt++)
#pragma unroll
            for (int r = 0; r < 4; r++) denom[mt][nt][r] = 0.0f;

    k1_stage(sb,         tid, (size_t)0 * ND + (size_t)q0 * D_, (size_t)0 * ND + (size_t)k0 * D_);
    k1_stage(sb + 24576, tid, (size_t)1 * ND + (size_t)q0 * D_, (size_t)1 * ND + (size_t)k0 * D_);

    for (int b = 0; b < B_; b++) {
        const uint32_t buf = sb + (b & 1) * 24576;
        if (b < B_ - 1) asm volatile("cp.async.wait_group 1;" ::: "memory");
        else            asm volatile("cp.async.wait_group 0;" ::: "memory");
        __syncthreads();

        float Dc[2][4][4];
#pragma unroll
        for (int mt = 0; mt < 2; mt++)
#pragma unroll
            for (int nt = 0; nt < 4; nt++)
#pragma unroll
                for (int r = 0; r < 4; r++) Dc[mt][nt][r] = 0.0f;

        mma_phase(buf, Dc, arow, brow, acol);

        // ---- exp + denom + fragment-tiled coalesced fp16 P store ----
        __half* Pb = g_P + (((size_t)b * 16 + qt) * 32 + kt) * TILE + fragoff;
#pragma unroll
        for (int mt = 0; mt < 2; mt++)
#pragma unroll
            for (int nt = 0; nt < 4; nt++) {
                float e0 = __expf(Dc[mt][nt][0]);
                float e1 = __expf(Dc[mt][nt][1]);
                float e2 = __expf(Dc[mt][nt][2]);
                float e3 = __expf(Dc[mt][nt][3]);
                denom[mt][nt][0] += e0; denom[mt][nt][1] += e1;
                denom[mt][nt][2] += e2; denom[mt][nt][3] += e3;
                *(uint2*)(Pb + (mt * 4 + nt) * 128) =
                    make_uint2(pack2h(e0, e1), pack2h(e2, e3));
            }
        __syncthreads();
        if (b + 2 < B_)
            k1_stage(buf, tid, (size_t)(b + 2) * ND + (size_t)q0 * D_,
                               (size_t)(b + 2) * ND + (size_t)k0 * D_);
    }

    // ---- rdenom (fragment-tiled, coalesced, fp32) ----
    float* Rb = g_rdenom + ((size_t)qt * 32 + kt) * TILE + fragoff;
#pragma unroll
    for (int mt = 0; mt < 2; mt++)
#pragma unroll
        for (int nt = 0; nt < 4; nt++)
            *(float4*)(Rb + (mt * 4 + nt) * 128) = make_float4(
                1.0f / denom[mt][nt][0], 1.0f / denom[mt][nt][1],
                1.0f / denom[mt][nt][2], 1.0f / denom[mt][nt][3]);
}

// ===========================================================================
// k2: out[b] = (P[b]*rdenom) @ V[b]. Block (b, qt), 256 thr.
// A = fp16(P)*rdenom, single plane; V single fp16.
// ALL operands via coalesced LDG; no smem/sync in main loop.
// ===========================================================================
__global__ __launch_bounds__(256, 2) void k2_out(float* __restrict__ O) {
    __shared__ __align__(16) float red[8192];   // 32KB, epilogue only
    const int tid = threadIdx.x;
    const int lane = tid & 31, w = tid >> 5;
    const int b = blockIdx.x, qt = blockIdx.y;
    const int wq2 = w >> 1, kh = w & 1;
    const int fragoff = w * 1024 + lane * 4;

    float Dc[2][8][4];
#pragma unroll
    for (int mt = 0; mt < 2; mt++)
#pragma unroll
        for (int j = 0; j < 8; j++)
#pragma unroll
            for (int r = 0; r < 4; r++) Dc[mt][j][r] = 0.0f;

    for (int c = 0; c < 32; c++) {
        const __half* pA = g_P + (((size_t)b * 16 + qt) * 32 + c) * TILE + fragoff;
        const float* pR = g_rdenom + ((size_t)qt * 32 + c) * TILE + fragoff;
        const size_t vbase = ((size_t)(b * 32 + c) * 16 + kh * 8) * 32 + lane;

#pragma unroll
        for (int kg = 0; kg < 2; kg++) {
            uint32_t aH[2][4];
#pragma unroll
            for (int mt = 0; mt < 2; mt++)
#pragma unroll
                for (int hf = 0; hf < 2; hf++) {
                    int i = mt * 4 + kg * 2 + hf;
                    uint2 pv = *(const uint2*)(pA + i * 128);
                    float4 r = *(const float4*)(pR + i * 128);
                    float2 p01 = __half22float2(*(__half2*)&pv.x);
                    float2 p23 = __half22float2(*(__half2*)&pv.y);
                    aH[mt][hf * 2]     = pack2h(p01.x * r.x, p01.y * r.y);
                    aH[mt][hf * 2 + 1] = pack2h(p23.x * r.z, p23.y * r.w);
                }
#pragma unroll
            for (int g16 = 0; g16 < 4; g16++) {
                uint4 vh = g_VFf[vbase + (size_t)(kg * 4 + g16) * 32];
#pragma unroll
                for (int mt = 0; mt < 2; mt++) {
                    mma16816(Dc[mt][g16 * 2],     aH[mt], vh.x, vh.z);
                    mma16816(Dc[mt][g16 * 2 + 1], aH[mt], vh.y, vh.w);
                }
            }
        }
    }

    // ---- cross-warp (kh) reduction via smem, then O store ----
    if (kh == 1) {
#pragma unroll
        for (int mt = 0; mt < 2; mt++)
#pragma unroll
            for (int j = 0; j < 8; j++)
                *(float4*)(red + wq2 * 2048 + (mt * 8 + j) * 128 + lane * 4) =
                    make_float4(Dc[mt][j][0], Dc[mt][j][1], Dc[mt][j][2], Dc[mt][j][3]);
    }
    __syncthreads();
    if (kh == 0) {
#pragma unroll
        for (int mt = 0; mt < 2; mt++) {
            int r0 = qt * 128 + wq2 * 32 + mt * 16 + (lane >> 2);
#pragma unroll
            for (int j = 0; j < 8; j++) {
                float4 o = *(float4*)(red + wq2 * 2048 + (mt * 8 + j) * 128 + lane * 4);
                float v0 = Dc[mt][j][0] + o.x;
                float v1 = Dc[mt][j][1] + o.y;
                float v2 = Dc[mt][j][2] + o.z;
                float v3 = Dc[mt][j][3] + o.w;
                int cc = j * 8 + 2 * (lane & 3);
                *(float2*)(O + ((size_t)b * N_ + r0) * D_ + cc)     = make_float2(v0, v1);
                *(float2*)(O + ((size_t)b * N_ + r0 + 8) * D_ + cc) = make_float2(v2, v3);
            }
        }
    }
}

// ===========================================================================
extern "C" void kernel_launch(void* const* d_in, const int* in_sizes, int n_in,
                              void* d_out, int out_size) {
    const float* Q = (const float*)d_in[0];
    const float* K = (const float*)d_in[1];
    const float* V = (const float*)d_in[2];
    float* O = (float*)d_out;

    cudaFuncSetAttribute(k1_scores, cudaFuncAttributeMaxDynamicSharedMemorySize, 49152);

    k0_prep<<<2560, 256>>>(Q, K, V);
    k1_scores<<<dim3(N_ / 64, N_ / 128), 256, 49152>>>();   // (kt, qt)
    k2_out<<<dim3(B_, N_ / 128), 256>>>(O);                 // (b, qt)
}